// round 1
// baseline (speedup 1.0000x reference)
#include <cuda_runtime.h>

// y = (U kron I2) @ x, U[i,i+1] = sqrt(i+1)
// x: (2D, B) fp32, D=4096, B=4096.
// out[r*B + b] = sqrt(r/2 + 1) * x[(r+2)*B + b]   for r < 2D-2
// out[r*B + b] = 0                                 for r in {2D-2, 2D-1}
//
// Pure shift-and-scale: HBM-bound, 256 MiB total traffic.
// float4 vectorization; B/4 = 1024 = 2^10 so row = idx >> 10.

static constexpr int D = 4096;
static constexpr int B = 4096;
static constexpr int B4 = B / 4;            // 1024 float4 per row
static constexpr int TOTAL4 = 2 * D * B4;   // 8,388,608 float4 elements
static constexpr int LAST_ROW = 2 * D - 2;  // rows >= this are zero

__global__ void __launch_bounds__(256) destroy_kernel(const float4* __restrict__ in,
                                                      float4* __restrict__ out) {
    int idx = blockIdx.x * blockDim.x + threadIdx.x;
    if (idx >= TOTAL4) return;

    int row = idx >> 10;  // idx / B4
    if (row < LAST_ROW) {
        float coef = sqrtf((float)((row >> 1) + 1));
        float4 v = in[idx + 2 * B4];  // x[row + 2]
        v.x *= coef; v.y *= coef; v.z *= coef; v.w *= coef;
        out[idx] = v;
    } else {
        out[idx] = make_float4(0.f, 0.f, 0.f, 0.f);
    }
}

extern "C" void kernel_launch(void* const* d_in, const int* in_sizes, int n_in,
                              void* d_out, int out_size) {
    const float4* in = (const float4*)d_in[0];
    float4* out = (float4*)d_out;
    int threads = 256;
    int blocks = (TOTAL4 + threads - 1) / threads;  // 32768
    destroy_kernel<<<blocks, threads>>>(in, out);
}

// round 2
// speedup vs baseline: 1.0022x; 1.0022x over previous
#include <cuda_runtime.h>

// y = (U kron I2) @ x, U[i,i+1] = sqrt(i+1)
// x: (2D, B) fp32, D=4096, B=4096.
// out[r] = sqrt(r/2 + 1) * x[r+2]  (rowwise), last two rows zero.
//
// One block per row: row = blockIdx.x (uniform), coef uniform per block.
// 256 threads x 4 float4 = 1024 float4 = one full row.
// Streaming loads/stores (.cs) — zero reuse, don't thrash L2.

static constexpr int D = 4096;
static constexpr int B4 = 4096 / 4;         // 1024 float4 per row
static constexpr int NROWS = 2 * D;         // 8192
static constexpr int LAST_ROW = NROWS - 2;

__global__ void __launch_bounds__(256) destroy_kernel(const float4* __restrict__ in,
                                                      float4* __restrict__ out) {
    const int row = blockIdx.x;
    const int tid = threadIdx.x;
    float4* orow = out + (size_t)row * B4;

    if (row < LAST_ROW) {
        const float coef = sqrtf((float)((row >> 1) + 1));
        const float4* irow = in + (size_t)(row + 2) * B4;

        // Front-batch 4 independent 16B loads (MLP=4), then scale+store.
        float4 v0 = __ldcs(irow + tid);
        float4 v1 = __ldcs(irow + tid + 256);
        float4 v2 = __ldcs(irow + tid + 512);
        float4 v3 = __ldcs(irow + tid + 768);

        v0.x *= coef; v0.y *= coef; v0.z *= coef; v0.w *= coef;
        v1.x *= coef; v1.y *= coef; v1.z *= coef; v1.w *= coef;
        v2.x *= coef; v2.y *= coef; v2.z *= coef; v2.w *= coef;
        v3.x *= coef; v3.y *= coef; v3.z *= coef; v3.w *= coef;

        __stcs(orow + tid,       v0);
        __stcs(orow + tid + 256, v1);
        __stcs(orow + tid + 512, v2);
        __stcs(orow + tid + 768, v3);
    } else {
        const float4 z = make_float4(0.f, 0.f, 0.f, 0.f);
        __stcs(orow + tid,       z);
        __stcs(orow + tid + 256, z);
        __stcs(orow + tid + 512, z);
        __stcs(orow + tid + 768, z);
    }
}

extern "C" void kernel_launch(void* const* d_in, const int* in_sizes, int n_in,
                              void* d_out, int out_size) {
    const float4* in = (const float4*)d_in[0];
    float4* out = (float4*)d_out;
    destroy_kernel<<<NROWS, 256>>>(in, out);
}